// round 6
// baseline (speedup 1.0000x reference)
#include <cuda_runtime.h>
#include <cuda_bf16.h>

#define NROWS  8192
#define DIM    1024
#define NPAIRS 1024
#define MARGIN_RANK 0.05f
#define FULL   0xFFFFFFFFu

// ---------------- device scratch (no allocations allowed) ----------------
__device__ float g_sp[NROWS];        // dp * rsqrt(|row|^2)  (row order, no text norm)
__device__ float g_sn[NROWS];        // dn * rsqrt(|row|^2)
__device__ int   g_ridx[NROWS];      // bucket-sorted slot -> row index
__device__ int   g_bstart[NPAIRS+1]; // exclusive starts + sentinel NROWS
__device__ float g_invp, g_invn;     // text-vector inverse norms
__device__ float g_cons_sum, g_pos_sum, g_neg_sum;
__device__ int   g_cons_cnt, g_rank_cnt;
__device__ int   g_done;

// ---------------- K1: block 0 = prep, blocks 1..1024 = GEMV --------------
// Prep (histogram/scan/index on one SM) runs concurrently with 1024 GEMV
// blocks that saturate HBM on the remaining SMs.
__global__ void __launch_bounds__(256) K1(
    const float4* __restrict__ x, const float* __restrict__ tp,
    const float* __restrict__ tn, const int* __restrict__ pair)
{
    __shared__ int            scnt[NPAIRS];    // histogram counts
    __shared__ int            sstart[NPAIRS];  // exclusive starts
    __shared__ unsigned short srank[NROWS];    // per-row rank within its bucket
    __shared__ int            wtot[8];
    __shared__ float          sA[8], sB[8];

    int t    = threadIdx.x;
    int lane = t & 31;
    int w    = t >> 5;

    if (blockIdx.x == 0) {
        // ---------------- prep path (256 threads) ----------------
        #pragma unroll
        for (int j = 0; j < 4; j++) scnt[t + j * 256] = 0;
        if (t == 0) {
            g_cons_sum = 0.f; g_pos_sum = 0.f; g_neg_sum = 0.f;
            g_cons_cnt = 0;   g_rank_cnt = 0;  g_done = 0;
            g_bstart[NPAIRS] = NROWS;          // sentinel for K2 staging
        }

        // text-vector inverse norms
        float pa = 0.f, pb = 0.f;
        #pragma unroll
        for (int j = 0; j < 4; j++) {
            float a = tp[t + j * 256];
            float b = tn[t + j * 256];
            pa += a * a;  pb += b * b;
        }
        #pragma unroll
        for (int o = 16; o; o >>= 1) {
            pa += __shfl_xor_sync(FULL, pa, o);
            pb += __shfl_xor_sync(FULL, pb, o);
        }
        if (lane == 0) { sA[w] = pa; sB[w] = pb; }
        __syncthreads();
        if (t == 0) {
            float qa = 0.f, qb = 0.f;
            #pragma unroll
            for (int j = 0; j < 8; j++) { qa += sA[j]; qb += sB[j]; }
            g_invp = rsqrtf(qa);
            g_invn = rsqrtf(qb);
        }
        __syncthreads();

        // histogram with rank capture (shared atomics)
        #pragma unroll 8
        for (int j = 0; j < 32; j++) {
            int i = t + j * 256;
            srank[i] = (unsigned short)atomicAdd(&scnt[pair[i]], 1);
        }
        __syncthreads();

        // exclusive scan over 1024 counts; thread owns buckets 4t..4t+3
        int s0 = scnt[4 * t + 0], s1 = scnt[4 * t + 1];
        int s2 = scnt[4 * t + 2], s3 = scnt[4 * t + 3];
        int tot = s0 + s1 + s2 + s3;
        int inc = tot;
        #pragma unroll
        for (int o = 1; o < 32; o <<= 1) {
            int n = __shfl_up_sync(FULL, inc, o);
            if (lane >= o) inc += n;
        }
        if (lane == 31) wtot[w] = inc;
        __syncthreads();
        if (t == 0) {
            int acc = 0;
            #pragma unroll
            for (int j = 0; j < 8; j++) { int v = wtot[j]; wtot[j] = acc; acc += v; }
        }
        __syncthreads();
        int base = wtot[w] + inc - tot;       // exclusive base for bucket 4t
        sstart[4 * t + 0] = base;  g_bstart[4 * t + 0] = base;  base += s0;
        sstart[4 * t + 1] = base;  g_bstart[4 * t + 1] = base;  base += s1;
        sstart[4 * t + 2] = base;  g_bstart[4 * t + 2] = base;  base += s2;
        sstart[4 * t + 3] = base;  g_bstart[4 * t + 3] = base;
        __syncthreads();

        // scatter row indices into bucket-sorted slots
        #pragma unroll 8
        for (int j = 0; j < 32; j++) {
            int i = t + j * 256;
            g_ridx[sstart[pair[i]] + (int)srank[i]] = i;
        }
    } else {
        // ---------------- GEMV path: one warp per row ----------------
        int row  = (blockIdx.x - 1) * 8 + w;
        const float4* r4  = x + (size_t)row * (DIM / 4);
        const float4* tp4 = (const float4*)tp;
        const float4* tn4 = (const float4*)tn;

        // 8 independent row loads in flight
        float4 v[8];
        #pragma unroll
        for (int k = 0; k < 8; k++) v[k] = r4[k * 32 + lane];

        float dp = 0.f, dn = 0.f, dx = 0.f;
        #pragma unroll
        for (int k = 0; k < 8; k++) {
            float4 p = __ldg(tp4 + k * 32 + lane);
            float4 q = __ldg(tn4 + k * 32 + lane);
            dp += v[k].x*p.x + v[k].y*p.y + v[k].z*p.z + v[k].w*p.w;
            dn += v[k].x*q.x + v[k].y*q.y + v[k].z*q.z + v[k].w*q.w;
            dx += v[k].x*v[k].x + v[k].y*v[k].y + v[k].z*v[k].z + v[k].w*v[k].w;
        }
        #pragma unroll
        for (int o = 16; o; o >>= 1) {
            dp += __shfl_xor_sync(FULL, dp, o);
            dn += __shfl_xor_sync(FULL, dn, o);
            dx += __shfl_xor_sync(FULL, dx, o);
        }
        if (lane == 0) {
            float inv = rsqrtf(dx);
            g_sp[row] = dp * inv;
            g_sn[row] = dn * inv;
        }
    }
}

// ---------------- K2: block-staged per-bucket all-pairs + finalize --------
// Block b owns buckets [8b, 8b+8) = contiguous slot range. All 256 threads
// gather {sp,sn,lev} into shared with full MLP; warps then run the shuffle
// all-pairs loop against shared memory (no global chains).
__global__ void __launch_bounds__(256) K2_pairs(const int* __restrict__ lev,
                                                float* __restrict__ out) {
    __shared__ float ssp[512], ssn[512];
    __shared__ int   slv[512];
    __shared__ int   sbs[9];
    __shared__ float sinv[2];

    int t = threadIdx.x, lane = t & 31, w = t >> 5;
    if (t < 9)  sbs[t] = g_bstart[blockIdx.x * 8 + t];
    if (t == 9) { sinv[0] = g_invp; sinv[1] = g_invn; }
    __syncthreads();

    int lo = sbs[0];
    int n  = sbs[8] - lo;
    bool staged = (n <= 512);
    if (staged) {
        for (int i = t; i < n; i += 256) {
            int r = g_ridx[lo + i];          // coalesced
            ssp[i] = g_sp[r] * sinv[0];      // 3 gathers in flight together
            ssn[i] = g_sn[r] * sinv[1];
            slv[i] = lev[r];
        }
    }
    __syncthreads();

    int start = sbs[w] - lo;                 // this warp's bucket, local offset
    int c     = sbs[w + 1] - sbs[w];

    float cs = 0.f, ps = 0.f, ns = 0.f;
    int cc = 0, rc = 0;

    if (staged && c <= 32) {
        float sp = 0.f, sn = 0.f; int lv = 0;
        bool act = lane < c;
        if (act) { sp = ssp[start + lane]; sn = ssn[start + lane]; lv = slv[start + lane]; }
        for (int b = 0; b < c; b++) {
            float spb = __shfl_sync(FULL, sp, b);
            float snb = __shfl_sync(FULL, sn, b);
            int   lb  = __shfl_sync(FULL, lv, b);
            if (act && lv == lb && lane < b) {
                cs += fabsf(sp - spb) + fabsf(sn - snb);
                cc++;
            }
            if (act && lv < lb) {
                ps += fmaxf(MARGIN_RANK - (sp - spb), 0.f);
                ns += fmaxf(MARGIN_RANK + (sn - snb), 0.f);
                rc++;
            }
        }
    } else {
        // fallback for improbable oversize buckets/ranges (global indirection)
        int gstart = sbs[w];
        for (int a = lane; a < c; a += 32) {
            int ra = g_ridx[gstart + a];
            float spa = g_sp[ra] * sinv[0];
            float sna = g_sn[ra] * sinv[1];
            int   la  = lev[ra];
            for (int b = 0; b < c; b++) {
                int rb = g_ridx[gstart + b];
                float spb = g_sp[rb] * sinv[0];
                float snb = g_sn[rb] * sinv[1];
                int   lb  = lev[rb];
                if (la == lb && a < b) {
                    cs += fabsf(spa - spb) + fabsf(sna - snb);
                    cc++;
                }
                if (la < lb) {
                    ps += fmaxf(MARGIN_RANK - (spa - spb), 0.f);
                    ns += fmaxf(MARGIN_RANK + (sna - snb), 0.f);
                    rc++;
                }
            }
        }
    }

    #pragma unroll
    for (int o = 16; o; o >>= 1) {
        cs += __shfl_xor_sync(FULL, cs, o);
        ps += __shfl_xor_sync(FULL, ps, o);
        ns += __shfl_xor_sync(FULL, ns, o);
        cc += __shfl_xor_sync(FULL, cc, o);
        rc += __shfl_xor_sync(FULL, rc, o);
    }
    if (lane == 0 && (cc | rc)) {
        atomicAdd(&g_cons_sum, cs);
        atomicAdd(&g_pos_sum,  ps);
        atomicAdd(&g_neg_sum,  ns);
        atomicAdd(&g_cons_cnt, cc);
        atomicAdd(&g_rank_cnt, rc);
    }

    // fused finalize: last block writes the scalar
    __syncthreads();
    if (threadIdx.x == 0) {
        __threadfence();
        if (atomicAdd(&g_done, 1) == (int)gridDim.x - 1) {
            __threadfence();
            float lc = (g_cons_cnt > 0) ? g_cons_sum / (float)(2 * g_cons_cnt) : 0.f;
            float lp = (g_rank_cnt > 0) ? g_pos_sum  / (float)g_rank_cnt       : 0.f;
            float ln = (g_rank_cnt > 0) ? g_neg_sum  / (float)g_rank_cnt       : 0.f;
            out[0] = lc + lp + ln;
        }
    }
}

// ---------------- launch ---------------------------------------------------
extern "C" void kernel_launch(void* const* d_in, const int* in_sizes, int n_in,
                              void* d_out, int out_size) {
    const float* img  = (const float*)d_in[0];  // [8192, 1024]
    const float* tp   = (const float*)d_in[1];  // [1024]
    const float* tn   = (const float*)d_in[2];  // [1024]
    const int*   lev  = (const int*)  d_in[3];  // [8192]
    const int*   pair = (const int*)  d_in[4];  // [8192]
    float* out = (float*)d_out;

    K1<<<1 + NROWS / 8, 256>>>((const float4*)img, tp, tn, pair);
    K2_pairs<<<NPAIRS / 8, 256>>>(lev, out);
}

// round 7
// speedup vs baseline: 1.0282x; 1.0282x over previous
#include <cuda_runtime.h>
#include <cuda_bf16.h>

#define NROWS  8192
#define DIM    1024
#define NPAIRS 1024
#define MARGIN_RANK 0.05f
#define FULL   0xFFFFFFFFu
#define GRID_BLOCKS 513     // 1 prep + 512 GEMV; all co-resident (>=4 blocks/SM)
#define PAIR_BLOCKS 128     // 8 warps x 128 blocks = 1024 buckets

// ---------------- device scratch (no allocations allowed) ----------------
__device__ float g_sp[NROWS];        // dp * rsqrt(|row|^2)  (row order, no text norm)
__device__ float g_sn[NROWS];        // dn * rsqrt(|row|^2)
__device__ int   g_ridx[NROWS];      // bucket-sorted slot -> row index
__device__ int   g_bstart[NPAIRS+1]; // exclusive starts + sentinel NROWS
__device__ float g_invp, g_invn;     // text-vector inverse norms
__device__ float g_cons_sum, g_pos_sum, g_neg_sum;
__device__ int   g_cons_cnt, g_rank_cnt;
__device__ int   g_arrive, g_done;   // barrier/finalize counters (reset each launch)

// ---------------- single fused kernel -------------------------------------
// Phase 1: block 0 preps (histogram/scan/index/norms) while blocks 1..512
//          stream the GEMV (2 rows per warp).
// Barrier: software grid barrier (co-residency guaranteed by launch bounds).
// Phase 2: blocks 0..127 run the staged per-bucket all-pairs; last one
//          finalizes the scalar and resets the counters for graph replay.
__global__ void __launch_bounds__(256, 4) K_fused(
    const float4* __restrict__ x, const float* __restrict__ tp,
    const float* __restrict__ tn, const int* __restrict__ pair,
    const int* __restrict__ lev, float* __restrict__ out)
{
    __shared__ union {
        struct {
            int            scnt[NPAIRS];    // histogram counts
            int            sstart[NPAIRS];  // exclusive starts
            unsigned short srank[NROWS];    // per-row rank within its bucket
            int            wtot[8];
            float          sA[8], sB[8];
        } prep;                              // 24.6 KB
        struct {
            float ssp[512], ssn[512];
            int   slv[512];
            int   sbs[9];
            float sinv[2];
        } pr;                                // 6.1 KB
    } sh;

    int t    = threadIdx.x;
    int lane = t & 31;
    int w    = t >> 5;

    if (blockIdx.x == 0) {
        // ---------------- prep path (256 threads) ----------------
        #pragma unroll
        for (int j = 0; j < 4; j++) sh.prep.scnt[t + j * 256] = 0;
        if (t == 0) {
            g_cons_sum = 0.f; g_pos_sum = 0.f; g_neg_sum = 0.f;
            g_cons_cnt = 0;   g_rank_cnt = 0;
            g_bstart[NPAIRS] = NROWS;          // sentinel for staging
        }

        // text-vector inverse norms
        float pa = 0.f, pb = 0.f;
        #pragma unroll
        for (int j = 0; j < 4; j++) {
            float a = tp[t + j * 256];
            float b = tn[t + j * 256];
            pa += a * a;  pb += b * b;
        }
        #pragma unroll
        for (int o = 16; o; o >>= 1) {
            pa += __shfl_xor_sync(FULL, pa, o);
            pb += __shfl_xor_sync(FULL, pb, o);
        }
        if (lane == 0) { sh.prep.sA[w] = pa; sh.prep.sB[w] = pb; }
        __syncthreads();
        if (t == 0) {
            float qa = 0.f, qb = 0.f;
            #pragma unroll
            for (int j = 0; j < 8; j++) { qa += sh.prep.sA[j]; qb += sh.prep.sB[j]; }
            g_invp = rsqrtf(qa);
            g_invn = rsqrtf(qb);
        }
        __syncthreads();

        // histogram with rank capture (shared atomics)
        #pragma unroll 8
        for (int j = 0; j < 32; j++) {
            int i = t + j * 256;
            sh.prep.srank[i] = (unsigned short)atomicAdd(&sh.prep.scnt[pair[i]], 1);
        }
        __syncthreads();

        // exclusive scan over 1024 counts; thread owns buckets 4t..4t+3
        int s0 = sh.prep.scnt[4 * t + 0], s1 = sh.prep.scnt[4 * t + 1];
        int s2 = sh.prep.scnt[4 * t + 2], s3 = sh.prep.scnt[4 * t + 3];
        int tot = s0 + s1 + s2 + s3;
        int inc = tot;
        #pragma unroll
        for (int o = 1; o < 32; o <<= 1) {
            int n = __shfl_up_sync(FULL, inc, o);
            if (lane >= o) inc += n;
        }
        if (lane == 31) sh.prep.wtot[w] = inc;
        __syncthreads();
        if (t == 0) {
            int acc = 0;
            #pragma unroll
            for (int j = 0; j < 8; j++) {
                int v = sh.prep.wtot[j]; sh.prep.wtot[j] = acc; acc += v;
            }
        }
        __syncthreads();
        int base = sh.prep.wtot[w] + inc - tot;       // exclusive base for bucket 4t
        sh.prep.sstart[4*t+0] = base;  g_bstart[4*t+0] = base;  base += s0;
        sh.prep.sstart[4*t+1] = base;  g_bstart[4*t+1] = base;  base += s1;
        sh.prep.sstart[4*t+2] = base;  g_bstart[4*t+2] = base;  base += s2;
        sh.prep.sstart[4*t+3] = base;  g_bstart[4*t+3] = base;
        __syncthreads();

        // scatter row indices into bucket-sorted slots
        #pragma unroll 8
        for (int j = 0; j < 32; j++) {
            int i = t + j * 256;
            g_ridx[sh.prep.sstart[pair[i]] + (int)sh.prep.srank[i]] = i;
        }
    } else {
        // ---------------- GEMV path: 2 rows per warp ----------------
        int rbase = (blockIdx.x - 1) * 16 + w * 2;
        const float4* tp4 = (const float4*)tp;
        const float4* tn4 = (const float4*)tn;

        #pragma unroll
        for (int r = 0; r < 2; r++) {
            int row = rbase + r;
            const float4* r4 = x + (size_t)row * (DIM / 4);

            float4 v[8];
            #pragma unroll
            for (int k = 0; k < 8; k++) v[k] = r4[k * 32 + lane];

            float dp = 0.f, dn = 0.f, dx = 0.f;
            #pragma unroll
            for (int k = 0; k < 8; k++) {
                float4 p = __ldg(tp4 + k * 32 + lane);
                float4 q = __ldg(tn4 + k * 32 + lane);
                dp += v[k].x*p.x + v[k].y*p.y + v[k].z*p.z + v[k].w*p.w;
                dn += v[k].x*q.x + v[k].y*q.y + v[k].z*q.z + v[k].w*q.w;
                dx += v[k].x*v[k].x + v[k].y*v[k].y + v[k].z*v[k].z + v[k].w*v[k].w;
            }
            #pragma unroll
            for (int o = 16; o; o >>= 1) {
                dp += __shfl_xor_sync(FULL, dp, o);
                dn += __shfl_xor_sync(FULL, dn, o);
                dx += __shfl_xor_sync(FULL, dx, o);
            }
            if (lane == 0) {
                float inv = rsqrtf(dx);
                g_sp[row] = dp * inv;
                g_sn[row] = dn * inv;
            }
        }
    }

    // ---------------- software grid barrier ----------------
    __syncthreads();
    if (t == 0) {
        __threadfence();                     // publish this block's writes
        atomicAdd(&g_arrive, 1);
        while (*((volatile int*)&g_arrive) < GRID_BLOCKS) { }
    }
    __syncthreads();
    __threadfence();                         // acquire: see all blocks' writes

    if (blockIdx.x >= PAIR_BLOCKS) return;

    // ---------------- pairs phase: block owns 8 contiguous buckets --------
    if (t < 9)  sh.pr.sbs[t] = g_bstart[blockIdx.x * 8 + t];
    if (t == 9) { sh.pr.sinv[0] = g_invp; sh.pr.sinv[1] = g_invn; }
    __syncthreads();

    int lo = sh.pr.sbs[0];
    int n  = sh.pr.sbs[8] - lo;
    bool staged = (n <= 512);
    if (staged) {
        for (int i = t; i < n; i += 256) {
            int r = g_ridx[lo + i];            // coalesced
            sh.pr.ssp[i] = g_sp[r] * sh.pr.sinv[0];
            sh.pr.ssn[i] = g_sn[r] * sh.pr.sinv[1];
            sh.pr.slv[i] = lev[r];
        }
    }
    __syncthreads();

    int start = sh.pr.sbs[w] - lo;             // this warp's bucket, local offset
    int c     = sh.pr.sbs[w + 1] - sh.pr.sbs[w];

    float cs = 0.f, ps = 0.f, ns = 0.f;
    int cc = 0, rc = 0;

    if (staged && c <= 32) {
        float sp = 0.f, sn = 0.f; int lv = 0;
        bool act = lane < c;
        if (act) {
            sp = sh.pr.ssp[start + lane];
            sn = sh.pr.ssn[start + lane];
            lv = sh.pr.slv[start + lane];
        }
        for (int b = 0; b < c; b++) {
            float spb = __shfl_sync(FULL, sp, b);
            float snb = __shfl_sync(FULL, sn, b);
            int   lb  = __shfl_sync(FULL, lv, b);
            if (act && lv == lb && lane < b) {
                cs += fabsf(sp - spb) + fabsf(sn - snb);
                cc++;
            }
            if (act && lv < lb) {
                ps += fmaxf(MARGIN_RANK - (sp - spb), 0.f);
                ns += fmaxf(MARGIN_RANK + (sn - snb), 0.f);
                rc++;
            }
        }
    } else {
        // fallback for improbable oversize buckets/ranges (global indirection)
        int gstart = sh.pr.sbs[w];
        float invp = g_invp, invn = g_invn;
        for (int a = lane; a < c; a += 32) {
            int ra = g_ridx[gstart + a];
            float spa = g_sp[ra] * invp;
            float sna = g_sn[ra] * invn;
            int   la  = lev[ra];
            for (int b = 0; b < c; b++) {
                int rb = g_ridx[gstart + b];
                float spb = g_sp[rb] * invp;
                float snb = g_sn[rb] * invn;
                int   lb  = lev[rb];
                if (la == lb && a < b) {
                    cs += fabsf(spa - spb) + fabsf(sna - snb);
                    cc++;
                }
                if (la < lb) {
                    ps += fmaxf(MARGIN_RANK - (spa - spb), 0.f);
                    ns += fmaxf(MARGIN_RANK + (sna - snb), 0.f);
                    rc++;
                }
            }
        }
    }

    #pragma unroll
    for (int o = 16; o; o >>= 1) {
        cs += __shfl_xor_sync(FULL, cs, o);
        ps += __shfl_xor_sync(FULL, ps, o);
        ns += __shfl_xor_sync(FULL, ns, o);
        cc += __shfl_xor_sync(FULL, cc, o);
        rc += __shfl_xor_sync(FULL, rc, o);
    }
    if (lane == 0 && (cc | rc)) {
        atomicAdd(&g_cons_sum, cs);
        atomicAdd(&g_pos_sum,  ps);
        atomicAdd(&g_neg_sum,  ns);
        atomicAdd(&g_cons_cnt, cc);
        atomicAdd(&g_rank_cnt, rc);
    }

    // fused finalize: last pairs-block writes the scalar + resets counters
    __syncthreads();
    if (t == 0) {
        __threadfence();
        if (atomicAdd(&g_done, 1) == PAIR_BLOCKS - 1) {
            __threadfence();
            float lc = (g_cons_cnt > 0) ? g_cons_sum / (float)(2 * g_cons_cnt) : 0.f;
            float lp = (g_rank_cnt > 0) ? g_pos_sum  / (float)g_rank_cnt       : 0.f;
            float ln = (g_rank_cnt > 0) ? g_neg_sum  / (float)g_rank_cnt       : 0.f;
            out[0] = lc + lp + ln;
            g_done   = 0;              // reset for next graph replay
            g_arrive = 0;
        }
    }
}

// ---------------- launch ---------------------------------------------------
extern "C" void kernel_launch(void* const* d_in, const int* in_sizes, int n_in,
                              void* d_out, int out_size) {
    const float* img  = (const float*)d_in[0];  // [8192, 1024]
    const float* tp   = (const float*)d_in[1];  // [1024]
    const float* tn   = (const float*)d_in[2];  // [1024]
    const int*   lev  = (const int*)  d_in[3];  // [8192]
    const int*   pair = (const int*)  d_in[4];  // [8192]
    float* out = (float*)d_out;

    K_fused<<<GRID_BLOCKS, 256>>>((const float4*)img, tp, tn, pair, lev, out);
}